// round 4
// baseline (speedup 1.0000x reference)
#include <cuda_runtime.h>
#include <cuda_bf16.h>
#include <math.h>

#define T_LEN    8192
#define VOCAB    50257
#define NCHUNK   74               // 8 qblocks x 74 chunks = 592 CTAs = 4/SM, 32 warps/SM
#define NQBLK    8
#define QBLK     1024             // queries per CTA
#define NTHREADS 256
#define QPT      4
#define KMAX     111              // ceil(8192/74)
#define NCTAS    (NQBLK * NCHUNK) // 592

// scratch (device globals; no allocation allowed)
__device__ float4 g_qp[T_LEN];                // q' = QSCALE * Wk^T Wq p   (x,y,z,0)
__device__ float4 g_p[T_LEN];                 // p with w=1.0f
__device__ float4 g_part[NCHUNK * T_LEN];     // per-chunk partial (sum e*p, sum e)
__device__ unsigned g_bar;                    // monotonic ticket barrier

__device__ __forceinline__ float ex2f(float x) {
    float r; asm("ex2.approx.f32 %0, %1;" : "=f"(r) : "f"(x)); return r;
}

// ---------------------------------------------------------------------------
// Kernel 1: gather + posenc; emit p and q' = QSCALE*(Wk^T Wq) p.
// k, v are never materialized: s_ij = q'_i . p_j, out = Wv (sum e p)/sum e.
// ---------------------------------------------------------------------------
__global__ __launch_bounds__(256)
void prep_kernel(const int* __restrict__ x,
                 const float* __restrict__ emb,
                 const float* __restrict__ Wk,
                 const float* __restrict__ Wq) {
    int t = blockIdx.x * blockDim.x + threadIdx.x;
    if (t >= T_LEN) return;

    int xi = x[t];
    xi = min(max(xi, 0), VOCAB - 1);

    // positional encoding — mirror reference fp32 op order
    float a  = 6.28f * (float)t;
    float p0 = emb[xi * 3 + 0] + cosf(a / 25.0f);
    float p1 = emb[xi * 3 + 1] + sinf(a / 25.0f);
    float p2 = emb[xi * 3 + 2] + sinf(a / 5.0f);

    const float QSCALE = 0.8329465708f;  // log2(e) / sqrt(3)

    // M = Wk^T Wq : M[c][b] = sum_a Wk[a][c] * Wq[a][b]
    float q0 = 0.f, q1 = 0.f, q2 = 0.f;
    #pragma unroll
    for (int aa = 0; aa < 3; ++aa) {
        float k0 = Wk[aa * 3 + 0], k1 = Wk[aa * 3 + 1], k2 = Wk[aa * 3 + 2];
        float qq = fmaf(Wq[aa * 3 + 0], p0,
                   fmaf(Wq[aa * 3 + 1], p1, Wq[aa * 3 + 2] * p2)); // (Wq p)_a
        q0 = fmaf(k0, qq, q0);
        q1 = fmaf(k1, qq, q1);
        q2 = fmaf(k2, qq, q2);
    }
    g_qp[t] = make_float4(q0 * QSCALE, q1 * QSCALE, q2 * QSCALE, 0.0f);
    g_p[t]  = make_float4(p0, p1, p2, 1.0f);
}

// ---------------------------------------------------------------------------
// Kernel 2: fused attention + in-kernel reduce (one-wave grid barrier).
// grid = (8, 74) = 592 CTAs x 256 threads = exactly 4 CTAs/SM, 8 warps/SMSP.
// ---------------------------------------------------------------------------
__global__ __launch_bounds__(NTHREADS, 4)
void attn_kernel(const float* __restrict__ Wv, float* __restrict__ out) {
    __shared__ float4 sp[KMAX];

    const int tid  = threadIdx.x;
    const int c    = blockIdx.y;
    const int kbeg = (c * T_LEN) / NCHUNK;
    const int kend = ((c + 1) * T_LEN) / NCHUNK;
    const int klen = kend - kbeg;

    for (int i = tid; i < klen; i += NTHREADS)
        sp[i] = g_p[kbeg + i];
    __syncthreads();

    const int qbase = blockIdx.x * QBLK + tid;
    float3 q[QPT];
    #pragma unroll
    for (int u = 0; u < QPT; ++u) {
        float4 t4 = g_qp[qbase + u * NTHREADS];
        q[u] = make_float3(t4.x, t4.y, t4.z);
    }

    float den[QPT], a0[QPT], a1[QPT], a2[QPT];
    #pragma unroll
    for (int u = 0; u < QPT; ++u) { den[u] = a0[u] = a1[u] = a2[u] = 0.0f; }

    #pragma unroll 3
    for (int j = 0; j < klen; ++j) {
        float4 p = sp[j];
        #pragma unroll
        for (int u = 0; u < QPT; ++u) {
            float s = fmaf(q[u].x, p.x, fmaf(q[u].y, p.y, q[u].z * p.z));
            float e = ex2f(s);
            den[u] += e;
            a0[u] = fmaf(e, p.x, a0[u]);
            a1[u] = fmaf(e, p.y, a1[u]);
            a2[u] = fmaf(e, p.z, a2[u]);
        }
    }

    #pragma unroll
    for (int u = 0; u < QPT; ++u)
        g_part[c * T_LEN + qbase + u * NTHREADS] =
            make_float4(a0[u], a1[u], a2[u], den[u]);

    // ---- one-wave grid barrier (ticket-monotonic: graph-replay safe) ----
    __threadfence();
    __syncthreads();
    if (tid == 0) {
        unsigned ticket = atomicAdd(&g_bar, 1u);
        unsigned target = (ticket / NCTAS + 1u) * NCTAS;
        volatile unsigned* vb = &g_bar;
        while (*vb < target) { __nanosleep(64); }
    }
    __syncthreads();
    __threadfence();

    // ---- fused reduce: CTA r handles queries [r*14, r*14+14) ----
    const int bid = blockIdx.y * NQBLK + blockIdx.x;   // 0..591
    if (tid < 14) {
        int qq = bid * 14 + tid;
        if (qq < T_LEN) {
            float r0 = 0.f, r1 = 0.f, r2 = 0.f, rd = 0.f;
            #pragma unroll 2
            for (int s = 0; s < NCHUNK; ++s) {
                float4 pp = g_part[s * T_LEN + qq];
                r0 += pp.x; r1 += pp.y; r2 += pp.z; rd += pp.w;
            }
            float inv = 1.0f / rd;
            // out = Wv . (sum e p) / den   (Wv row-major (out,in))
            out[qq * 3 + 0] = fmaf(Wv[0], r0, fmaf(Wv[1], r1, Wv[2] * r2)) * inv;
            out[qq * 3 + 1] = fmaf(Wv[3], r0, fmaf(Wv[4], r1, Wv[5] * r2)) * inv;
            out[qq * 3 + 2] = fmaf(Wv[6], r0, fmaf(Wv[7], r1, Wv[8] * r2)) * inv;
        }
    }
}

extern "C" void kernel_launch(void* const* d_in, const int* in_sizes, int n_in,
                              void* d_out, int out_size) {
    const int*   x   = (const int*)  d_in[0];
    const float* emb = (const float*)d_in[1];
    const float* Wk  = (const float*)d_in[2];
    const float* Wq  = (const float*)d_in[3];
    const float* Wv  = (const float*)d_in[4];
    float* out = (float*)d_out;

    prep_kernel<<<T_LEN / 256, 256>>>(x, emb, Wk, Wq);
    attn_kernel<<<dim3(NQBLK, NCHUNK), NTHREADS>>>(Wv, out);
}